// round 8
// baseline (speedup 1.0000x reference)
#include <cuda_runtime.h>
#include <cstdint>

#define N_VOX   262144
#define M_PAIRS 131072
#define K_OFF   27
#define C       32
#define CPAD    36        // row stride in floats: 16B pad -> halves hit disjoint banks

// ---------------------------------------------------------------------------
// Kernel 1: out[n][c] = bias[c]  (bias add commutes with the scatter-adds)
// ---------------------------------------------------------------------------
__global__ void bias_init_kernel(float* __restrict__ out,
                                 const float* __restrict__ bias)
{
    int t = blockIdx.x * blockDim.x + threadIdx.x;
    const int total4 = N_VOX * (C / 4);
    if (t < total4) {
        const float4* b4 = (const float4*)bias;
        float4* o4 = (float4*)out;
        o4[t] = b4[t & 7];
    }
}

// ---------------------------------------------------------------------------
// Kernel 2: staged gather -> smem -> f32x2 GEMM (2 pairs/warp) -> red.v2.
//
//   Stage:  256 rows gathered coalesced (8 lanes x float4 per row) into
//           padded smem rows (stride 36 floats).
//   Math:   each 16-lane half-warp owns one pair; lane covers 2 channels
//           (one f32x2 accumulator). Each LDS.128 feeds TWO pairs ->
//           4 LDS/pair instead of 8; padding makes the 2-address LDS
//           conflict-free.
//   Scatter: red.global.add.v2.f32 per lane (contiguous 128B per pair).
// ---------------------------------------------------------------------------
#define THREADS          256
#define WARPS_PER_BLOCK  8
#define PAIRS_PER_BLOCK  256
#define PAIRS_PER_WARP   (PAIRS_PER_BLOCK / WARPS_PER_BLOCK)   // 32
#define STEPS            (PAIRS_PER_WARP / 2)                  // 16 (2 pairs/step)

__global__ __launch_bounds__(THREADS)
void scatter_gemm_kernel(const float* __restrict__ input,
                         const float* __restrict__ kernel,
                         const int*   __restrict__ in_map,
                         const int*   __restrict__ out_map,
                         float*       __restrict__ out)
{
    __shared__ float srow[PAIRS_PER_BLOCK][CPAD];    // 36 KB staged rows

    const int k     = blockIdx.y;
    const int lane  = threadIdx.x & 31;
    const int warp  = threadIdx.x >> 5;
    const int half  = lane >> 4;          // which pair of the step
    const int chalf = lane & 15;          // channel pair: covers 2*chalf, 2*chalf+1

    const int tile = blockIdx.x * PAIRS_PER_BLOCK;
    const int* im  = in_map  + k * M_PAIRS + tile;
    const int* om  = out_map + k * M_PAIRS + tile;

    // ---- Stage: 256 rows x 8 quads, coalesced; 8 float4 per thread.
    #pragma unroll
    for (int i = 0; i < (PAIRS_PER_BLOCK * (C / 4)) / THREADS; i++) {
        int q  = threadIdx.x + i * THREADS;
        int pr = q >> 3;
        int qq = q & 7;
        int irow = __ldg(im + pr);
        ((float4*)&srow[pr][0])[qq] =
            __ldg((const float4*)(input + (size_t)irow * C) + qq);
    }

    // ---- Weights: lane's 2 output channels, packed f32x2 per input channel.
    const float* Wk = kernel + k * C * C;
    unsigned long long wp[C];
    #pragma unroll
    for (int i = 0; i < C; i++) {
        float2 w2 = __ldg((const float2*)(Wk + i * C) + chalf);
        asm("mov.b64 %0, {%1, %2};" : "=l"(wp[i]) : "f"(w2.x), "f"(w2.y));
    }

    __syncthreads();

    const int pbase = warp * PAIRS_PER_WARP;

    #pragma unroll 4
    for (int t = 0; t < STEPS; t++) {
        const int pr   = pbase + 2 * t + half;
        const int orow = __ldg(om + pr);        // 2 distinct addrs per warp

        const float4* r4 = (const float4*)&srow[pr][0];

        unsigned long long acc = 0ULL;          // packed (0.f, 0.f)
        #pragma unroll
        for (int j = 0; j < C / 4; j++) {
            float4 a = r4[j];                   // 2-addr LDS.128, conflict-free
            unsigned long long ax, ay, az, aw;
            asm("mov.b64 %0, {%1, %1};" : "=l"(ax) : "f"(a.x));
            asm("mov.b64 %0, {%1, %1};" : "=l"(ay) : "f"(a.y));
            asm("mov.b64 %0, {%1, %1};" : "=l"(az) : "f"(a.z));
            asm("mov.b64 %0, {%1, %1};" : "=l"(aw) : "f"(a.w));
            asm("fma.rn.f32x2 %0, %1, %2, %0;" : "+l"(acc) : "l"(ax), "l"(wp[4 * j + 0]));
            asm("fma.rn.f32x2 %0, %1, %2, %0;" : "+l"(acc) : "l"(ay), "l"(wp[4 * j + 1]));
            asm("fma.rn.f32x2 %0, %1, %2, %0;" : "+l"(acc) : "l"(az), "l"(wp[4 * j + 2]));
            asm("fma.rn.f32x2 %0, %1, %2, %0;" : "+l"(acc) : "l"(aw), "l"(wp[4 * j + 3]));
        }
        float lo, hi;
        asm("mov.b64 {%0, %1}, %2;" : "=f"(lo), "=f"(hi) : "l"(acc));

        float* dst = out + (size_t)orow * C + 2 * chalf;   // 8B aligned
        asm volatile("red.global.add.v2.f32 [%0], {%1, %2};"
                     :: "l"(dst), "f"(lo), "f"(hi) : "memory");
    }
}

// ---------------------------------------------------------------------------
// Launch
// ---------------------------------------------------------------------------
extern "C" void kernel_launch(void* const* d_in, const int* in_sizes, int n_in,
                              void* d_out, int out_size)
{
    const float* input   = (const float*)d_in[0];
    const float* kernelw = (const float*)d_in[1];
    const float* bias    = (const float*)d_in[2];
    const int*   in_map  = (const int*)  d_in[3];
    const int*   out_map = (const int*)  d_in[4];
    float*       out     = (float*)d_out;

    const int total4 = N_VOX * (C / 4);
    bias_init_kernel<<<(total4 + 255) / 256, 256>>>(out, bias);

    dim3 grid(M_PAIRS / PAIRS_PER_BLOCK, K_OFF);
    scatter_gemm_kernel<<<grid, THREADS>>>(input, kernelw, in_map, out_map, out);
}

// round 9
// speedup vs baseline: 1.1246x; 1.1246x over previous
#include <cuda_runtime.h>
#include <cstdint>

#define N_VOX   262144
#define M_PAIRS 131072
#define K_OFF   27
#define C       32
#define CPAD    36        // row stride in floats (144B = 16B-aligned, banks shifted by 4)

// ---------------------------------------------------------------------------
// Kernel 1: out[n][c] = bias[c]  (bias add commutes with the scatter-adds)
// ---------------------------------------------------------------------------
__global__ void bias_init_kernel(float* __restrict__ out,
                                 const float* __restrict__ bias)
{
    int t = blockIdx.x * blockDim.x + threadIdx.x;
    const int total4 = N_VOX * (C / 4);
    if (t < total4) {
        const float4* b4 = (const float4*)bias;
        float4* o4 = (float4*)out;
        o4[t] = b4[t & 7];
    }
}

// ---------------------------------------------------------------------------
// Kernel 2: staged gather -> smem -> input-packed f32x2 GEMM -> red.v2.
//
//   Each 16-lane half-warp owns one pair; lane covers channels (2c, 2c+1).
//   Input row is read as ulonglong2 (LDS.128 -> two packed f32x2 input
//   pairs), consumed DIRECTLY by fma.rn.f32x2 against input-pair-packed
//   weights: zero replication movs. Two packed accumulators (one per
//   output channel) hold (even-input, odd-input) partials; one horizontal
//   add each at the end.
// ---------------------------------------------------------------------------
#define THREADS          128
#define WARPS_PER_BLOCK  4
#define PAIRS_PER_BLOCK  128
#define PAIRS_PER_WARP   32
#define STEPS            16            // 2 pairs per step (one per half-warp)

__global__ __launch_bounds__(THREADS)
void scatter_gemm_kernel(const float* __restrict__ input,
                         const float* __restrict__ kernel,
                         const int*   __restrict__ in_map,
                         const int*   __restrict__ out_map,
                         float*       __restrict__ out)
{
    __shared__ float srow[PAIRS_PER_BLOCK][CPAD];    // 18 KB staged rows

    const int k     = blockIdx.y;
    const int lane  = threadIdx.x & 31;
    const int warp  = threadIdx.x >> 5;
    const int half  = lane >> 4;          // which pair of the step
    const int chalf = lane & 15;          // covers channels 2*chalf, 2*chalf+1

    const int tile = blockIdx.x * PAIRS_PER_BLOCK;
    const int* im  = in_map  + k * M_PAIRS + tile;
    const int* om  = out_map + k * M_PAIRS + tile;

    // ---- Stage: 128 rows x 8 quads, coalesced; 8 float4 per thread.
    #pragma unroll
    for (int i = 0; i < (PAIRS_PER_BLOCK * (C / 4)) / THREADS; i++) {
        int q  = threadIdx.x + i * THREADS;
        int pr = q >> 3;
        int qq = q & 7;
        int irow = __ldg(im + pr);
        ((float4*)&srow[pr][0])[qq] =
            __ldg((const float4*)(input + (size_t)irow * C) + qq);
    }

    // ---- Weights, input-pair packed:
    //   wA[i] = (W[2i][c0], W[2i+1][c0]),  wB[i] = (W[2i][c1], W[2i+1][c1])
    const float* Wk = kernel + k * C * C;
    unsigned long long wA[C / 2], wB[C / 2];
    #pragma unroll
    for (int i = 0; i < C / 2; i++) {
        float2 f = __ldg((const float2*)(Wk + (2 * i)     * C) + chalf); // (W[2i][c0],  W[2i][c1])
        float2 g = __ldg((const float2*)(Wk + (2 * i + 1) * C) + chalf); // (W[2i+1][c0],W[2i+1][c1])
        asm("mov.b64 %0, {%1, %2};" : "=l"(wA[i]) : "f"(f.x), "f"(g.x));
        asm("mov.b64 %0, {%1, %2};" : "=l"(wB[i]) : "f"(f.y), "f"(g.y));
    }

    __syncthreads();

    const int pbase = warp * PAIRS_PER_WARP;

    #pragma unroll 4
    for (int t = 0; t < STEPS; t++) {
        const int pr   = pbase + 2 * t + half;
        const int orow = __ldg(om + pr);        // 2 distinct addrs per warp

        const ulonglong2* r2 = (const ulonglong2*)&srow[pr][0];

        unsigned long long accA = 0ULL, accB = 0ULL;   // packed (even, odd) partials
        #pragma unroll
        for (int j = 0; j < C / 4; j++) {
            ulonglong2 a = r2[j];               // LDS.128: (in[4j],in[4j+1]),(in[4j+2],in[4j+3])
            asm("fma.rn.f32x2 %0, %1, %2, %0;" : "+l"(accA) : "l"(a.x), "l"(wA[2 * j]));
            asm("fma.rn.f32x2 %0, %1, %2, %0;" : "+l"(accA) : "l"(a.y), "l"(wA[2 * j + 1]));
            asm("fma.rn.f32x2 %0, %1, %2, %0;" : "+l"(accB) : "l"(a.x), "l"(wB[2 * j]));
            asm("fma.rn.f32x2 %0, %1, %2, %0;" : "+l"(accB) : "l"(a.y), "l"(wB[2 * j + 1]));
        }
        float a0, a1, b0, b1;
        asm("mov.b64 {%0, %1}, %2;" : "=f"(a0), "=f"(a1) : "l"(accA));
        asm("mov.b64 {%0, %1}, %2;" : "=f"(b0), "=f"(b1) : "l"(accB));
        const float c0 = a0 + a1;
        const float c1 = b0 + b1;

        float* dst = out + (size_t)orow * C + 2 * chalf;   // 8B aligned
        asm volatile("red.global.add.v2.f32 [%0], {%1, %2};"
                     :: "l"(dst), "f"(c0), "f"(c1) : "memory");
    }
}

// ---------------------------------------------------------------------------
// Launch
// ---------------------------------------------------------------------------
extern "C" void kernel_launch(void* const* d_in, const int* in_sizes, int n_in,
                              void* d_out, int out_size)
{
    const float* input   = (const float*)d_in[0];
    const float* kernelw = (const float*)d_in[1];
    const float* bias    = (const float*)d_in[2];
    const int*   in_map  = (const int*)  d_in[3];
    const int*   out_map = (const int*)  d_in[4];
    float*       out     = (float*)d_out;

    const int total4 = N_VOX * (C / 4);
    bias_init_kernel<<<(total4 + 255) / 256, 256>>>(out, bias);

    dim3 grid(M_PAIRS / PAIRS_PER_BLOCK, K_OFF);
    scatter_gemm_kernel<<<grid, THREADS>>>(input, kernelw, in_map, out_map, out);
}